// round 17
// baseline (speedup 1.0000x reference)
#include <cuda_runtime.h>
#include <cuda_fp16.h>
#include <cstdint>

#define S_ 1024
#define B_ 8
#define H_ 1024
#define T_ 8192
#define E_ 8
#define F_ 4096
#define NASSIGN (T_*2)
#define MAXROWS (NASSIGN + E_*128)
#define MAXTILES (MAXROWS/128)
#define W1TILES 16384            // (F/32)*(H/64)*E
#define PREPBLKS (W1TILES + MAXROWS)
#define W2FOLDROWS 4             // extra grid.y rows at the FRONT of gemm1 (128 blocks)

// GEMM tiling: CTA 128x128, 8 warps x (64x32), K-chunk 64, 3-stage cp.async
#define KC 64
#define AST 144
#define TILEB (128*AST)
#define NSTAGE 3
#define SMEMSZ (NSTAGE*2*TILEB)   // 110592

// ---- static device scratch ----
__device__ __half g_w1t[(size_t)E_*F_*H_];   // [e][f][h] fp16, k-major rows
__device__ __half g_w2t[(size_t)E_*H_*F_];   // [e][h][f] fp16, k-major rows
__device__ __half g_xh[(size_t)MAXROWS*H_];
__device__ __half g_hbuf[(size_t)MAXROWS*F_];
__device__ int   g_tileExpert[MAXTILES];
__device__ int   g_rowToken[MAXROWS];
__device__ float g_rowCoef[MAXROWS];

__device__ __forceinline__ uint32_t smem_u32(const void* p){
    uint32_t a; asm("{ .reg .u64 t; cvta.to.shared.u64 t, %1; cvt.u32.u64 %0, t; }":"=r"(a):"l"(p)); return a;
}
__device__ __forceinline__ void cp16(uint32_t d, const void* s){
    asm volatile("cp.async.cg.shared.global [%0], [%1], 16;"::"r"(d),"l"(s):"memory");
}
#define CP_COMMIT() asm volatile("cp.async.commit_group;":::"memory")
#define CP_WAIT(n)  asm volatile("cp.async.wait_group %0;"::"n"(n):"memory")

__device__ __forceinline__ void ldm4(uint32_t* r, uint32_t addr){
    asm volatile("ldmatrix.sync.aligned.m8n8.x4.shared.b16 {%0,%1,%2,%3}, [%4];"
        : "=r"(r[0]),"=r"(r[1]),"=r"(r[2]),"=r"(r[3]) : "r"(addr));
}
__device__ __forceinline__ void mma16816(float* c, const uint32_t* a, uint32_t b0, uint32_t b1){
    asm volatile("mma.sync.aligned.m16n8k16.row.col.f32.f16.f16.f32 "
        "{%0,%1,%2,%3},{%4,%5,%6,%7},{%8,%9},{%0,%1,%2,%3};"
        : "+f"(c[0]),"+f"(c[1]),"+f"(c[2]),"+f"(c[3])
        : "r"(a[0]),"r"(a[1]),"r"(a[2]),"r"(a[3]),"r"(b0),"r"(b1));
}

// ---- fused routing (single block); records per-row token + gate coefficient ----
__global__ void __launch_bounds__(1024) k_route(const void* __restrict__ ce,
                                                const float* __restrict__ gw){
    __shared__ int scount[E_], scursor[E_], sbase[E_];
    __shared__ int sis32;
    const int tid = threadIdx.x;
    if (tid < E_){ scount[tid]=0; scursor[tid]=0; }
    if (tid == 0) sis32 = 0;
    for (int i = tid; i < MAXROWS; i += 1024){ g_rowToken[i] = -1; g_rowCoef[i] = 0.f; }
    __syncthreads();
    const long long* c64 = (const long long*)ce;
    for (int a = tid; a < NASSIGN/2; a += 1024){
        long long v = c64[a];
        if (v < 0 || v >= E_) sis32 = 1;
    }
    __syncthreads();
    const int is32 = sis32;
    for (int a = tid; a < NASSIGN; a += 1024){
        int e = is32 ? ((const int*)ce)[a] : (int)c64[a];
        atomicAdd(&scount[e], 1);
    }
    __syncthreads();
    if (tid == 0){
        int acc = 0;
        for (int e = 0; e < E_; e++){ sbase[e] = acc; acc += ((scount[e]+127)/128)*128; }
        int t = 0;
        for (int e = 0; e < E_; e++){
            int nt = (scount[e]+127)/128;
            for (int i = 0; i < nt && t < MAXTILES; i++) g_tileExpert[t++] = e;
        }
        for (; t < MAXTILES; t++) g_tileExpert[t] = -1;
    }
    __syncthreads();
    for (int a = tid; a < NASSIGN; a += 1024){
        int e = is32 ? ((const int*)ce)[a] : (int)c64[a];
        int pos = sbase[e] + atomicAdd(&scursor[e], 1);
        g_rowToken[pos] = a >> 1;
        g_rowCoef[pos] = gw[a];
    }
}

// ---- fused prep: w1 transpose + token gather (w2t moved into gemm1's grid) ----
__global__ void __launch_bounds__(256) k_prep(const float* __restrict__ w1,
                                              const float* __restrict__ x){
    __shared__ float t[64][33];
    const int bid = blockIdx.x;
    const int tid = threadIdx.x, tx = tid & 31, ty = tid >> 5;
    if (bid < W1TILES){
        // w1 [E][H][F] -> g_w1t [E][F][H]; tile 64(h) x 32(f)
        int e = bid >> 11, r = bid & 2047;
        int fb = (r & 127)*32, hb = (r >> 7)*64;
        const float* src = w1 + (size_t)e*H_*F_;
        #pragma unroll
        for (int i = ty; i < 64; i += 8)
            t[i][tx] = src[(size_t)(hb+i)*F_ + fb + tx];
        __syncthreads();
        __half2* dst = (__half2*)(g_w1t + (size_t)e*F_*H_);
        #pragma unroll
        for (int i = ty; i < 32; i += 8){
            __half2 v = __floats2half2_rn(t[2*tx][i], t[2*tx+1][i]);
            dst[((size_t)(fb+i)*H_ + hb)/2 + tx] = v;
        }
    } else {
        // token gather fp32 -> fp16 per padded row
        int pos = bid - W1TILES;
        int tok = g_rowToken[pos];
        if (tok < 0) return;
        const float4* s = (const float4*)(x + (size_t)tok*H_);
        __half2* d = (__half2*)(g_xh + (size_t)pos*H_);
        float4 v = s[tid];
        d[2*tid]   = __floats2half2_rn(v.x, v.y);
        d[2*tid+1] = __floats2half2_rn(v.z, v.w);
    }
}

__device__ __forceinline__ float gelu_f(float v){
    float c = v + 0.044715f*v*v*v;
    return 0.5f*v*(1.0f + tanhf(0.7978845608028654f*c));
}

// ---- grouped GEMM (proven 485us mainloop): 128x128 CTA, 8 warps x (64x32) ----
// G1: grid.y = W2FOLDROWS + MAXTILES. The FIRST 128 blocks (tile_m < W2FOLDROWS)
//     stream-transpose w2 -> g_w2t (hidden under wave-1 GEMM compute). All G1
//     blocks also zero their slice of out. gemm1->gemm2 boundary orders both.
// G2: epilogue scatters coef-weighted fp32 results directly into out via atomicAdd.
template<bool G1>
__global__ void __launch_bounds__(256, 2) k_gemm(const float* __restrict__ w2src,
                                                 float* __restrict__ out){
    constexpr int Kd = G1 ? H_ : F_;
    constexpr int Nd = G1 ? F_ : H_;
    constexpr int NC = Kd/KC;
    extern __shared__ char smem[];
    const int tile_n = blockIdx.x, tile_my = blockIdx.y;
    const int tid = threadIdx.x;

    if (G1){
        // zero out's slice (all blocks participate, incl. transpose blocks)
        const int bid = tile_my*gridDim.x + tile_n;
        const int stride = gridDim.x*gridDim.y*256;
        float4* o4 = (float4*)out;
        for (int i = bid*256 + tid; i < T_*H_/4; i += stride)
            o4[i] = make_float4(0.f, 0.f, 0.f, 0.f);
    }

    if (G1 && tile_my < W2FOLDROWS){
        // w2 [E][F][H] -> g_w2t [E][H][F]; 128 fat blocks, 128 sub-tiles each
        const int blk = tile_my*32 + tile_n;          // [0,128)
        const int e2 = blk >> 4, sub = blk & 15;      // 16 blocks per expert
        const int tx = tid & 31, ty = tid >> 5;
        float* t = (float*)smem;                      // 64 x 33 floats
        const float* src = w2src + (size_t)e2*F_*H_;
        __half2* dst = (__half2*)(g_w2t + (size_t)e2*H_*F_);
        for (int fo = 0; fo < 4; fo++){               // 256 f-rows per block
            const int f0 = sub*256 + fo*64;
            for (int ho = 0; ho < 32; ho++){
                const int h0 = ho*32;
                #pragma unroll
                for (int i = ty; i < 64; i += 8)
                    t[i*33 + tx] = src[(size_t)(f0+i)*H_ + h0 + tx];
                __syncthreads();
                #pragma unroll
                for (int i = ty; i < 32; i += 8){
                    __half2 v = __floats2half2_rn(t[(2*tx)*33 + i], t[(2*tx+1)*33 + i]);
                    dst[((size_t)(h0+i)*F_ + f0)/2 + tx] = v;
                }
                __syncthreads();
            }
        }
        return;
    }

    const int tile_m = G1 ? (tile_my - W2FOLDROWS) : tile_my;
    const int e = g_tileExpert[tile_m];
    if (e < 0) return;
    const __half* A = G1 ? g_xh : g_hbuf;
    const __half* Bt = (G1 ? g_w1t : g_w2t) + (size_t)e*Nd*Kd;
    const int wid = tid>>5, lane = tid&31;
    const int wm = wid & 1, wn = wid >> 1;
    const uint32_t sA = smem_u32(smem);
    const int rowA0 = tile_m*128, colB0 = tile_n*128;

    auto loadChunk = [&](int c, int st){
        const int kb = c*KC;
        const uint32_t base = sA + st*2*TILEB;
        #pragma unroll
        for (int i = 0; i < 4; i++){
            int idx = i*256 + tid;
            int row = idx >> 3, seg = idx & 7;
            cp16(base + row*AST + seg*16,
                 A + (size_t)(rowA0+row)*Kd + kb + seg*8);
        }
        #pragma unroll
        for (int i = 0; i < 4; i++){
            int idx = i*256 + tid;
            int row = idx >> 3, seg = idx & 7;
            cp16(base + TILEB + row*AST + seg*16,
                 Bt + (size_t)(colB0+row)*Kd + kb + seg*8);
        }
        CP_COMMIT();
    };

    float acc[4][4][4];
    float* accp = &acc[0][0][0];
    #pragma unroll
    for (int i = 0; i < 64; i++) accp[i] = 0.f;

    loadChunk(0, 0);
    loadChunk(1, 1);
    const uint32_t lrow = (lane & 15);
    const uint32_t lcol = (lane >> 4)*16;
    const uint32_t aOff = (wm*64 + lrow)*AST + lcol;
    const uint32_t bOff = (wn*32 + lrow)*AST + lcol;
    int st = 0;
    for (int c = 0; c < NC; c++){
        if (c + 1 < NC){ CP_WAIT(1); } else { CP_WAIT(0); }
        __syncthreads();
        if (c + 2 < NC){
            int ns = st + 2; if (ns >= NSTAGE) ns -= NSTAGE;
            loadChunk(c+2, ns);
        }
        const uint32_t aRow = sA + st*2*TILEB + aOff;
        const uint32_t bRow = sA + st*2*TILEB + TILEB + bOff;
        #pragma unroll
        for (int k16 = 0; k16 < 4; k16++){
            const uint32_t ko = k16*32;
            uint32_t af[4][4], bf[2][4];
            #pragma unroll
            for (int mi = 0; mi < 4; mi++) ldm4(af[mi], aRow + mi*(16*AST) + ko);
            #pragma unroll
            for (int li = 0; li < 2; li++) ldm4(bf[li], bRow + li*(16*AST) + ko);
            #pragma unroll
            for (int mi = 0; mi < 4; mi++){
                #pragma unroll
                for (int li = 0; li < 2; li++){
                    mma16816(acc[mi][li*2+0], af[mi], bf[li][0], bf[li][2]);
                    mma16816(acc[mi][li*2+1], af[mi], bf[li][1], bf[li][3]);
                }
            }
        }
        if (++st >= NSTAGE) st = 0;
    }

    // epilogue
    const int r0 = rowA0 + wm*64 + (lane>>2);
    const int c0 = colB0 + wn*32 + (lane&3)*2;
    #pragma unroll
    for (int mi = 0; mi < 4; mi++){
        const int rowA_ = r0 + mi*16, rowB_ = rowA_ + 8;
        if (G1){
            #pragma unroll
            for (int ni = 0; ni < 4; ni++){
                int col = c0 + ni*8;
                __half* hb = g_hbuf;
                *(__half2*)(hb + (size_t)rowA_*Nd + col) =
                    __floats2half2_rn(gelu_f(acc[mi][ni][0]), gelu_f(acc[mi][ni][1]));
                *(__half2*)(hb + (size_t)rowB_*Nd + col) =
                    __floats2half2_rn(gelu_f(acc[mi][ni][2]), gelu_f(acc[mi][ni][3]));
            }
        } else {
            const int tokA = g_rowToken[rowA_], tokB = g_rowToken[rowB_];
            const float cA = g_rowCoef[rowA_],  cB = g_rowCoef[rowB_];
            #pragma unroll
            for (int ni = 0; ni < 4; ni++){
                int col = c0 + ni*8;
                if (tokA >= 0){
                    atomicAdd(&out[(size_t)tokA*H_ + col],     cA*acc[mi][ni][0]);
                    atomicAdd(&out[(size_t)tokA*H_ + col + 1], cA*acc[mi][ni][1]);
                }
                if (tokB >= 0){
                    atomicAdd(&out[(size_t)tokB*H_ + col],     cB*acc[mi][ni][2]);
                    atomicAdd(&out[(size_t)tokB*H_ + col + 1], cB*acc[mi][ni][3]);
                }
            }
        }
    }
}

extern "C" void kernel_launch(void* const* d_in, const int* in_sizes, int n_in,
                              void* d_out, int out_size){
    const float* x  = (const float*)d_in[0];
    const float* gw = (const float*)d_in[1];
    const void*  ce = d_in[2];
    const float* w1 = (const float*)d_in[3];
    const float* w2 = (const float*)d_in[4];
    float* out = (float*)d_out;

    cudaFuncSetAttribute(k_gemm<true>,  cudaFuncAttributeMaxDynamicSharedMemorySize, SMEMSZ);
    cudaFuncSetAttribute(k_gemm<false>, cudaFuncAttributeMaxDynamicSharedMemorySize, SMEMSZ);

    k_route<<<1, 1024>>>(ce, gw);
    k_prep<<<PREPBLKS, 256>>>(w1, x);
    k_gemm<true><<<dim3(F_/128, W2FOLDROWS + MAXTILES), 256, SMEMSZ>>>(w2, out);
    k_gemm<false><<<dim3(H_/128, MAXTILES), 256, SMEMSZ>>>(w2, out);
}